// round 9
// baseline (speedup 1.0000x reference)
#include <cuda_runtime.h>
#include <cuda_bf16.h>
#include <cstdint>

// ===========================================================================
// Problem: B=32, T=128, F=1024, CONV_UNITS=2048, SHORT_UNITS=2048, RATE=4
//   out[b, 0:2016,    :] = memory[b, 32:2048,   :]
//   out[b, 2016:2048, :] = compression (GEMM)
//   out[b, 2048:3968, :] = memory[b, 2176:4096, :]
//   out[b, 3968:4096, :] = inputs[b, :, :]
// GEMM: C(1024x1024) = A(1024x4096) @ W(4096x1024) + bias
//   A row m=(b*32+t): 4096 contiguous floats at memory + b*2^22 + 2097152 + t*4096
//   W = conv_w viewed as (4096,1024) row-major.
//
// R8 ncu: GEMM tensor=28%, issue=24% with only a 2-chunk prefetch distance ->
// exposed global-load latency. This round: 6-stage cp.async pipeline
// (5-chunk / ~1400cyc cover) + single __syncthreads per chunk.
// ===========================================================================

#define CP_ASYNC16(dst, src) \
    asm volatile("cp.async.cg.shared.global [%0], [%1], 16;" \
                 :: "r"(dst), "l"(src) : "memory")
#define CP_ASYNC_COMMIT() asm volatile("cp.async.commit_group;" ::: "memory")
#define CP_ASYNC_WAIT4()  asm volatile("cp.async.wait_group 4;" ::: "memory")
#define CP_ASYNC_WAIT0()  asm volatile("cp.async.wait_group 0;" ::: "memory")

__device__ __forceinline__ uint32_t smem_u32(const void* p) {
    uint32_t a;
    asm("{ .reg .u64 t; cvta.to.shared.u64 t, %1; cvt.u32.u64 %0, t; }"
        : "=r"(a) : "l"(p));
    return a;
}

__device__ __forceinline__ void mma_tf32_16n8k8(float* c, const uint32_t* a,
                                                const uint32_t* b) {
    asm volatile(
        "mma.sync.aligned.m16n8k8.row.col.f32.tf32.tf32.f32 "
        "{%0,%1,%2,%3}, {%4,%5,%6,%7}, {%8,%9}, {%0,%1,%2,%3};"
        : "+f"(c[0]), "+f"(c[1]), "+f"(c[2]), "+f"(c[3])
        : "r"(a[0]), "r"(a[1]), "r"(a[2]), "r"(a[3]),
          "r"(b[0]), "r"(b[1]));
}

#define A_STRIDE 36
#define B_STRIDE 132
#define STAGE_BYTES 26112
#define NSTAGE 6

// ---------------------------------------------------------------------------
// Pipelined tf32 GEMM. CTA tile 64x128, K-chunk 32, 6-stage cp.async.
// Grid (8,16) = 128 CTAs, 256 threads / 8 warps.
// Warp map: ws = wid&3 spatial (wm=(ws&1)*32, wn=(ws>>1)*64, warp tile 32x64);
//           kh = wid>>2 K-half. End: kh=1 partials folded into kh=0 via smem.
// Loop order per chunk: wait_group 4 -> __syncthreads -> issue kc+5 (into the
// slot consumed LAST iteration, safe past the barrier) -> compute kc.
// PTX m16n8k8 tf32 A-fragment (g=lid>>2, t=lid&3):
//   a0=A[g][t] a1=A[g+8][t] a2=A[g][t+4] a3=A[g+8][t+4]
// B-fragment: b0=B[t][g], b1=B[t+4][g].  C: c0,c1=C[g][2t,2t+1]; c2,c3=C[g+8][..]
// ---------------------------------------------------------------------------
__global__ void __launch_bounds__(256, 1)
gemm_tf32(const float* __restrict__ memory,
          const float* __restrict__ W,
          const float* __restrict__ bias,
          float* __restrict__ out)
{
    extern __shared__ __align__(16) char smem[];
    const int tid = threadIdx.x;
    const int wid = tid >> 5;
    const int lid = tid & 31;
    const int m0 = blockIdx.y * 64;
    const int n0 = blockIdx.x * 128;
    const int ws = wid & 3;
    const int kh = wid >> 2;
    const int wm = (ws & 1) * 32;
    const int wn = (ws >> 1) * 64;

    float acc[2][8][4];
#pragma unroll
    for (int i = 0; i < 2; i++)
#pragma unroll
        for (int j = 0; j < 8; j++)
#pragma unroll
            for (int k = 0; k < 4; k++) acc[i][j][k] = 0.0f;

    auto issue_stage = [&](int kc) {
        const int s = kc % NSTAGE;
        char* sa = smem + s * STAGE_BYTES;
        char* sb = sa + 9216;
        const int k0 = kc << 5;
#pragma unroll
        for (int rep = 0; rep < 2; rep++) {
            const int i = tid + rep * 256;
            const int r = i >> 3, q = i & 7;
            const int m = m0 + r;
            const float* src = memory + ((size_t)(m >> 5) << 22) + 2097152u
                               + ((size_t)(m & 31) << 12) + (unsigned)(k0 + (q << 2));
            CP_ASYNC16(smem_u32(sa + (r * A_STRIDE + q * 4) * 4), src);
        }
#pragma unroll
        for (int rep = 0; rep < 4; rep++) {
            const int i = tid + rep * 256;
            const int r = i >> 5, q = i & 31;
            const float* src = W + (size_t)(k0 + r) * 1024u + (unsigned)(n0 + (q << 2));
            CP_ASYNC16(smem_u32(sb + (r * B_STRIDE + q * 4) * 4), src);
        }
    };

    // Prologue: 5 stages in flight.
#pragma unroll
    for (int p = 0; p < NSTAGE - 1; ++p) {
        issue_stage(p);
        CP_ASYNC_COMMIT();
    }

    for (int kc = 0; kc < 128; ++kc) {
        CP_ASYNC_WAIT4();        // stage kc resident
        __syncthreads();         // all threads done with slot (kc-1)%6

        if (kc + NSTAGE - 1 < 128) {
            issue_stage(kc + NSTAGE - 1);   // writes slot (kc-1)%6 — safe
            CP_ASYNC_COMMIT();
        }

        const int s = kc % NSTAGE;
        const float* sa = (const float*)(smem + s * STAGE_BYTES);
        const float* sb = (const float*)(smem + s * STAGE_BYTES + 9216);

#pragma unroll
        for (int ks2 = 0; ks2 < 2; ++ks2) {
            const int k = (kh * 2 + ks2) << 3;
            uint32_t af[2][4], bf[8][2];
            const int arow = wm + (lid >> 2);
            const int acol = k + (lid & 3);
#pragma unroll
            for (int mt = 0; mt < 2; mt++) {
                const float* ap = sa + (arow + mt * 16) * A_STRIDE + acol;
                af[mt][0] = __float_as_uint(ap[0]);                  // A[g][t]
                af[mt][1] = __float_as_uint(ap[8 * A_STRIDE]);       // A[g+8][t]
                af[mt][2] = __float_as_uint(ap[4]);                  // A[g][t+4]
                af[mt][3] = __float_as_uint(ap[8 * A_STRIDE + 4]);   // A[g+8][t+4]
            }
            const int brow = k + (lid & 3);
            const int bcol = wn + (lid >> 2);
#pragma unroll
            for (int nt = 0; nt < 8; nt++) {
                const float* bp = sb + brow * B_STRIDE + bcol + nt * 8;
                bf[nt][0] = __float_as_uint(bp[0]);                  // B[t][g]
                bf[nt][1] = __float_as_uint(bp[4 * B_STRIDE]);       // B[t+4][g]
            }
#pragma unroll
            for (int mt = 0; mt < 2; mt++)
#pragma unroll
                for (int nt = 0; nt < 8; nt++)
                    mma_tf32_16n8k8(acc[mt][nt], af[mt], bf[nt]);
        }
    }
    CP_ASYNC_WAIT0();
    __syncthreads();   // compute done everywhere; smem reusable as scratch

    // Intra-CTA K-split reduction: kh=1 warps dump partials, kh=0 warps fold.
    float* red = (float*)smem;          // 4 tiles x 2048 floats = 32KB
    if (kh == 1) {
#pragma unroll
        for (int mt = 0; mt < 2; mt++)
#pragma unroll
            for (int nt = 0; nt < 8; nt++)
#pragma unroll
                for (int c = 0; c < 4; c++) {
                    const int r = mt * 32 + nt * 4 + c;
                    red[ws * 2048 + r * 32 + lid] = acc[mt][nt][c];
                }
    }
    __syncthreads();
    if (kh == 0) {
#pragma unroll
        for (int mt = 0; mt < 2; mt++)
#pragma unroll
            for (int nt = 0; nt < 8; nt++)
#pragma unroll
                for (int c = 0; c < 4; c++) {
                    const int r = mt * 32 + nt * 4 + c;
                    acc[mt][nt][c] += red[ws * 2048 + r * 32 + lid];
                }

        // Epilogue: bias + direct float2 stores into the compression band.
#pragma unroll
        for (int mt = 0; mt < 2; mt++) {
#pragma unroll
            for (int nt = 0; nt < 8; nt++) {
                const int g = n0 + wn + nt * 8 + (lid & 3) * 2;
                const float2 bv = *(const float2*)(bias + g);
                const int m_lo = m0 + wm + mt * 16 + (lid >> 2);
                const int m_hi = m_lo + 8;
                float2 v0 = { acc[mt][nt][0] + bv.x, acc[mt][nt][1] + bv.y };
                float2 v1 = { acc[mt][nt][2] + bv.x, acc[mt][nt][3] + bv.y };
                *(float2*)(out + ((size_t)(m_lo >> 5) << 22)
                               + (size_t)(2016 + (m_lo & 31)) * 1024 + g) = v0;
                *(float2*)(out + ((size_t)(m_hi >> 5) << 22)
                               + (size_t)(2016 + (m_hi & 31)) * 1024 + g) = v1;
            }
        }
    }
}

// ---------------------------------------------------------------------------
// Copy kernel: pure shifted memcpy, float4-vectorized, grid-stride.
// ---------------------------------------------------------------------------
__global__ void copy_kernel(const float4* __restrict__ inputs,
                            const float4* __restrict__ memory,
                            float4* __restrict__ out)
{
    const unsigned total = 32u * 4096u * 256u;
    const unsigned stride = gridDim.x * blockDim.x;
    for (unsigned v = blockIdx.x * blockDim.x + threadIdx.x; v < total; v += stride) {
        unsigned f4 = v & 255u;
        unsigned rg = v >> 8;
        unsigned b  = rg >> 12;
        unsigned r  = rg & 4095u;
        float4 val;
        if (r < 2016u) {
            val = memory[(b << 20) + ((r + 32u) << 8) + f4];
        } else if (r < 2048u) {
            continue;  // compression band written by GEMM kernel
        } else if (r < 3968u) {
            val = memory[(b << 20) + ((r + 128u) << 8) + f4];
        } else {
            val = inputs[(b << 15) + ((r - 3968u) << 8) + f4];
        }
        out[v] = val;
    }
}

// ---------------------------------------------------------------------------
// Launch: serial — GEMM then copy.
// ---------------------------------------------------------------------------
extern "C" void kernel_launch(void* const* d_in, const int* in_sizes, int n_in,
                              void* d_out, int out_size)
{
    const float* inputs = (const float*)d_in[0];   // (32, 128, 1024)
    const float* memory = (const float*)d_in[1];   // (32, 4096, 1024)
    const float* conv_w = (const float*)d_in[2];   // (4, 1024, 1024)
    const float* conv_b = (const float*)d_in[3];   // (1024,)
    float* out = (float*)d_out;                    // (32, 4096, 1024)

    cudaFuncSetAttribute(gemm_tf32,
                         cudaFuncAttributeMaxDynamicSharedMemorySize,
                         STAGE_BYTES * NSTAGE);

    gemm_tf32<<<dim3(8, 16), 256, STAGE_BYTES * NSTAGE>>>(memory, conv_w,
                                                          conv_b, out);
    copy_kernel<<<8192, 256>>>((const float4*)inputs, (const float4*)memory,
                               (float4*)out);
}

// round 10
// speedup vs baseline: 1.1488x; 1.1488x over previous
#include <cuda_runtime.h>
#include <cuda_fp16.h>
#include <cstdint>

// ===========================================================================
// Problem: B=32, T=128, F=1024, CONV_UNITS=2048, SHORT_UNITS=2048, RATE=4
//   out[b, 0:2016,    :] = memory[b, 32:2048,   :]
//   out[b, 2016:2048, :] = compression (GEMM)
//   out[b, 2048:3968, :] = memory[b, 2176:4096, :]
//   out[b, 3968:4096, :] = inputs[b, :, :]
// GEMM: C(1024x1024) = A(1024x4096) @ W(4096x1024) + bias
//   A row m=(b*32+t): 4096 contiguous floats at memory + b*2^22 + 2097152 + t*4096
//
// R8/R9 showed the tf32 GEMM is MMA-ISSUE bound (~21 cyc per m16n8k8 per
// SMSP). Fix: fp16 m16n8k16 (same 10-bit mantissa as tf32, 2x MACs/instr).
// Pre-pass converts A -> fp16 and W -> fp16 TRANSPOSED so both fragment
// loads are k-contiguous vectorized LDS.32.
// ===========================================================================

#define CP_ASYNC16(dst, src) \
    asm volatile("cp.async.cg.shared.global [%0], [%1], 16;" \
                 :: "r"(dst), "l"(src) : "memory")
#define CP_ASYNC_COMMIT() asm volatile("cp.async.commit_group;" ::: "memory")
#define CP_ASYNC_WAIT2()  asm volatile("cp.async.wait_group 2;" ::: "memory")
#define CP_ASYNC_WAIT0()  asm volatile("cp.async.wait_group 0;" ::: "memory")

__device__ __forceinline__ uint32_t smem_u32(const void* p) {
    uint32_t a;
    asm("{ .reg .u64 t; cvta.to.shared.u64 t, %1; cvt.u32.u64 %0, t; }"
        : "=r"(a) : "l"(p));
    return a;
}

__device__ __forceinline__ void mma_f16_16n8k16(float* c, const uint32_t* a,
                                                const uint32_t* b) {
    asm volatile(
        "mma.sync.aligned.m16n8k16.row.col.f32.f16.f16.f32 "
        "{%0,%1,%2,%3}, {%4,%5,%6,%7}, {%8,%9}, {%0,%1,%2,%3};"
        : "+f"(c[0]), "+f"(c[1]), "+f"(c[2]), "+f"(c[3])
        : "r"(a[0]), "r"(a[1]), "r"(a[2]), "r"(a[3]),
          "r"(b[0]), "r"(b[1]));
}

// fp16 operand scratch: A (1024 x 4096) and W^T (1024 n x 4096 k), 8 MB each.
__device__ __half g_Ah[1024 * 4096];
__device__ __half g_Wth[1024 * 4096];

// ---------------------------------------------------------------------------
// Convert A (fp32 slices of `memory`) -> g_Ah fp16, k-contiguous rows.
// ---------------------------------------------------------------------------
__global__ void convert_a(const float* __restrict__ memory)
{
    const unsigned i = blockIdx.x * 256u + threadIdx.x;   // 1M threads, 4 f32 each
    const unsigned m = i >> 10;            // row 0..1023
    const unsigned kq = (i & 1023u) << 2;  // k offset 0..4092 step 4
    const float* src = memory + ((size_t)(m >> 5) << 22) + 2097152u
                       + ((size_t)(m & 31) << 12) + kq;
    float4 v = *(const float4*)src;
    __half2* dst = (__half2*)(g_Ah + (size_t)m * 4096u + kq);
    dst[0] = __floats2half2_rn(v.x, v.y);
    dst[1] = __floats2half2_rn(v.z, v.w);
}

// ---------------------------------------------------------------------------
// Convert + transpose W (4096 k x 1024 n f32) -> g_Wth (1024 n x 4096 k) fp16.
// ---------------------------------------------------------------------------
__global__ void convert_wt(const float* __restrict__ W)
{
    __shared__ __half tile[32][33];
    const int nb = blockIdx.x * 32;
    const int kb = blockIdx.y * 32;
    const int tx = threadIdx.x;
    for (int j = threadIdx.y; j < 32; j += 8)
        tile[j][tx] = __float2half(W[(size_t)(kb + j) * 1024 + nb + tx]);
    __syncthreads();
    for (int j = threadIdx.y; j < 32; j += 8)
        g_Wth[(size_t)(nb + j) * 4096 + kb + tx] = tile[tx][j];
}

// ---------------------------------------------------------------------------
// fp16 GEMM. CTA tile 64x128, K-chunk 64 halves, 4-stage cp.async.
// Grid (8,16) = 128 CTAs, 256 threads / 8 warps.
// Warp map: ws = wid&3 spatial (wm=(ws&1)*32, wn=(ws>>1)*64, warp tile 32x64);
//           kh = wid>>2 K-half (k16 steps kh*2, kh*2+1 of the 4 per chunk).
// Smem rows padded to 72 halves (144B = 36 banks -> conflict-free frags).
// PTX m16n8k16 f16 fragments (g=lid>>2, t=lid&3):
//   a0={A[g][2t,2t+1]} a1={A[g+8][2t,..]} a2={A[g][2t+8,..]} a3={A[g+8][2t+8,..]}
//   b0={B[2t][n],B[2t+1][n]} b1={B[2t+8][n],B[2t+9][n]}  (k-contig in Wt[n][k])
//   c0,c1=C[g][2t,2t+1]; c2,c3=C[g+8][2t,2t+1]
// ---------------------------------------------------------------------------
#define A_ST 72            // halves per A smem row
#define B_ST 72            // halves per B smem row
#define A_BYTES (64 * 144)     // 9216
#define STAGE_BYTES (64 * 144 + 128 * 144)   // 27648
#define NSTAGE 4

__global__ void __launch_bounds__(256, 1)
gemm_f16(const float* __restrict__ bias, float* __restrict__ out)
{
    extern __shared__ __align__(16) char smem[];
    const int tid = threadIdx.x;
    const int wid = tid >> 5;
    const int lid = tid & 31;
    const int m0 = blockIdx.y * 64;
    const int n0 = blockIdx.x * 128;
    const int ws = wid & 3;
    const int kh = wid >> 2;
    const int wm = (ws & 1) * 32;
    const int wn = (ws >> 1) * 64;

    float acc[2][8][4];
#pragma unroll
    for (int i = 0; i < 2; i++)
#pragma unroll
        for (int j = 0; j < 8; j++)
#pragma unroll
            for (int k = 0; k < 4; k++) acc[i][j][k] = 0.0f;

    auto issue_stage = [&](int kc) {
        const int s = kc % NSTAGE;
        char* sa = smem + s * STAGE_BYTES;
        char* sb = sa + A_BYTES;
        const unsigned k0 = (unsigned)kc << 6;          // 64 halves per chunk
        // A: 64 rows x 8 groups of 8 halves (16B) = 512 -> 2/thread
#pragma unroll
        for (int rep = 0; rep < 2; rep++) {
            const int i = tid + rep * 256;
            const int r = i >> 3, q = i & 7;
            const __half* src = g_Ah + (size_t)(m0 + r) * 4096u + k0 + (q << 3);
            CP_ASYNC16(smem_u32(sa + r * 144 + q * 16), src);
        }
        // B: 128 rows x 8 groups = 1024 -> 4/thread
#pragma unroll
        for (int rep = 0; rep < 4; rep++) {
            const int i = tid + rep * 256;
            const int r = i >> 3, q = i & 7;
            const __half* src = g_Wth + (size_t)(n0 + r) * 4096u + k0 + (q << 3);
            CP_ASYNC16(smem_u32(sb + r * 144 + q * 16), src);
        }
    };

    // Prologue: 3 stages in flight.
#pragma unroll
    for (int p = 0; p < NSTAGE - 1; ++p) {
        issue_stage(p);
        CP_ASYNC_COMMIT();
    }

    for (int kc = 0; kc < 64; ++kc) {
        CP_ASYNC_WAIT2();        // stage kc resident
        __syncthreads();         // everyone done with slot (kc-1)%4

        if (kc + NSTAGE - 1 < 64) {
            issue_stage(kc + NSTAGE - 1);   // writes slot (kc-1)%4 — safe
            CP_ASYNC_COMMIT();
        }

        const int s = kc % NSTAGE;
        const __half* sa = (const __half*)(smem + s * STAGE_BYTES);
        const __half* sb = (const __half*)(smem + s * STAGE_BYTES + A_BYTES);

#pragma unroll
        for (int ks2 = 0; ks2 < 2; ++ks2) {
            const int k = (kh * 2 + ks2) << 4;     // k16 step offset in halves
            uint32_t af[2][4], bf[8][2];
            const int arow = wm + (lid >> 2);
            const int acol = k + ((lid & 3) << 1);
#pragma unroll
            for (int mt = 0; mt < 2; mt++) {
                const __half* ap = sa + (arow + mt * 16) * A_ST + acol;
                af[mt][0] = *(const uint32_t*)(ap);                 // A[g][2t..]
                af[mt][1] = *(const uint32_t*)(ap + 8 * A_ST);      // A[g+8][2t..]
                af[mt][2] = *(const uint32_t*)(ap + 8);             // A[g][2t+8..]
                af[mt][3] = *(const uint32_t*)(ap + 8 * A_ST + 8);  // A[g+8][2t+8..]
            }
            const int bcol = wn + (lid >> 2);
#pragma unroll
            for (int nt = 0; nt < 8; nt++) {
                const __half* bp = sb + (bcol + nt * 8) * B_ST + acol;
                bf[nt][0] = *(const uint32_t*)(bp);        // B[2t..2t+1][n]
                bf[nt][1] = *(const uint32_t*)(bp + 8);    // B[2t+8..2t+9][n]
            }
#pragma unroll
            for (int mt = 0; mt < 2; mt++)
#pragma unroll
                for (int nt = 0; nt < 8; nt++)
                    mma_f16_16n8k16(acc[mt][nt], af[mt], bf[nt]);
        }
    }
    CP_ASYNC_WAIT0();
    __syncthreads();   // compute done; smem reusable as reduction scratch

    // Intra-CTA K-split reduction: kh=1 warps dump partials, kh=0 warps fold.
    float* red = (float*)smem;          // 4 tiles x 2048 floats = 32KB
    if (kh == 1) {
#pragma unroll
        for (int mt = 0; mt < 2; mt++)
#pragma unroll
            for (int nt = 0; nt < 8; nt++)
#pragma unroll
                for (int c = 0; c < 4; c++) {
                    const int r = mt * 32 + nt * 4 + c;
                    red[ws * 2048 + r * 32 + lid] = acc[mt][nt][c];
                }
    }
    __syncthreads();
    if (kh == 0) {
#pragma unroll
        for (int mt = 0; mt < 2; mt++)
#pragma unroll
            for (int nt = 0; nt < 8; nt++)
#pragma unroll
                for (int c = 0; c < 4; c++) {
                    const int r = mt * 32 + nt * 4 + c;
                    acc[mt][nt][c] += red[ws * 2048 + r * 32 + lid];
                }

        // Epilogue: bias + direct float2 stores into the compression band.
#pragma unroll
        for (int mt = 0; mt < 2; mt++) {
#pragma unroll
            for (int nt = 0; nt < 8; nt++) {
                const int g = n0 + wn + nt * 8 + (lid & 3) * 2;
                const float2 bv = *(const float2*)(bias + g);
                const int m_lo = m0 + wm + mt * 16 + (lid >> 2);
                const int m_hi = m_lo + 8;
                float2 v0 = { acc[mt][nt][0] + bv.x, acc[mt][nt][1] + bv.y };
                float2 v1 = { acc[mt][nt][2] + bv.x, acc[mt][nt][3] + bv.y };
                *(float2*)(out + ((size_t)(m_lo >> 5) << 22)
                               + (size_t)(2016 + (m_lo & 31)) * 1024 + g) = v0;
                *(float2*)(out + ((size_t)(m_hi >> 5) << 22)
                               + (size_t)(2016 + (m_hi & 31)) * 1024 + g) = v1;
            }
        }
    }
}

// ---------------------------------------------------------------------------
// Copy kernel: pure shifted memcpy, float4-vectorized, grid-stride.
// ---------------------------------------------------------------------------
__global__ void copy_kernel(const float4* __restrict__ inputs,
                            const float4* __restrict__ memory,
                            float4* __restrict__ out)
{
    const unsigned total = 32u * 4096u * 256u;
    const unsigned stride = gridDim.x * blockDim.x;
    for (unsigned v = blockIdx.x * blockDim.x + threadIdx.x; v < total; v += stride) {
        unsigned f4 = v & 255u;
        unsigned rg = v >> 8;
        unsigned b  = rg >> 12;
        unsigned r  = rg & 4095u;
        float4 val;
        if (r < 2016u) {
            val = memory[(b << 20) + ((r + 32u) << 8) + f4];
        } else if (r < 2048u) {
            continue;  // compression band written by GEMM kernel
        } else if (r < 3968u) {
            val = memory[(b << 20) + ((r + 128u) << 8) + f4];
        } else {
            val = inputs[(b << 15) + ((r - 3968u) << 8) + f4];
        }
        out[v] = val;
    }
}

// ---------------------------------------------------------------------------
// Launch: converts -> GEMM -> copy (serial; R5-R7 showed overlap loses).
// ---------------------------------------------------------------------------
extern "C" void kernel_launch(void* const* d_in, const int* in_sizes, int n_in,
                              void* d_out, int out_size)
{
    const float* inputs = (const float*)d_in[0];   // (32, 128, 1024)
    const float* memory = (const float*)d_in[1];   // (32, 4096, 1024)
    const float* conv_w = (const float*)d_in[2];   // (4, 1024, 1024)
    const float* conv_b = (const float*)d_in[3];   // (1024,)
    float* out = (float*)d_out;                    // (32, 4096, 1024)

    cudaFuncSetAttribute(gemm_f16,
                         cudaFuncAttributeMaxDynamicSharedMemorySize,
                         STAGE_BYTES * NSTAGE);

    convert_a<<<4096, 256>>>(memory);
    convert_wt<<<dim3(32, 128), dim3(32, 8)>>>(conv_w);
    gemm_f16<<<dim3(8, 16), 256, STAGE_BYTES * NSTAGE>>>(conv_b, out);
    copy_kernel<<<8192, 256>>>((const float4*)inputs, (const float4*)memory,
                               (float4*)out);
}

// round 11
// speedup vs baseline: 1.1544x; 1.0048x over previous
#include <cuda_runtime.h>
#include <cuda_fp16.h>
#include <cstdint>

// ===========================================================================
// Problem: B=32, T=128, F=1024, CONV_UNITS=2048, SHORT_UNITS=2048, RATE=4
//   out[b, 0:2016,    :] = memory[b, 32:2048,   :]
//   out[b, 2016:2048, :] = compression (GEMM)
//   out[b, 2048:3968, :] = memory[b, 2176:4096, :]
//   out[b, 3968:4096, :] = inputs[b, :, :]
// GEMM: C(1024x1024) = A(1024x4096) @ W(4096x1024) + bias
//   A row m=(b*32+t): 4096 contiguous floats at memory + b*2^22 + 2097152 + t*4096
//
// fp16 m16n8k16 datapath (R10 win). This round: ldmatrix.x4 fragment loads
// (12 shared-pipe instrs/chunk vs 48 scalar LDS) + fused convert kernel.
// Copy is at its ~6.7TB/s LTS floor; overlap attempts are retired (R5/R6).
// ===========================================================================

#define CP_ASYNC16(dst, src) \
    asm volatile("cp.async.cg.shared.global [%0], [%1], 16;" \
                 :: "r"(dst), "l"(src) : "memory")
#define CP_ASYNC_COMMIT() asm volatile("cp.async.commit_group;" ::: "memory")
#define CP_ASYNC_WAIT2()  asm volatile("cp.async.wait_group 2;" ::: "memory")
#define CP_ASYNC_WAIT0()  asm volatile("cp.async.wait_group 0;" ::: "memory")

__device__ __forceinline__ uint32_t smem_u32(const void* p) {
    uint32_t a;
    asm("{ .reg .u64 t; cvta.to.shared.u64 t, %1; cvt.u32.u64 %0, t; }"
        : "=r"(a) : "l"(p));
    return a;
}

__device__ __forceinline__ void ldmatrix_x4(uint32_t& r0, uint32_t& r1,
                                            uint32_t& r2, uint32_t& r3,
                                            uint32_t addr) {
    asm volatile("ldmatrix.sync.aligned.m8n8.x4.shared.b16 {%0,%1,%2,%3}, [%4];"
                 : "=r"(r0), "=r"(r1), "=r"(r2), "=r"(r3) : "r"(addr));
}

__device__ __forceinline__ void mma_f16_16n8k16(float* c, const uint32_t* a,
                                                const uint32_t* b) {
    asm volatile(
        "mma.sync.aligned.m16n8k16.row.col.f32.f16.f16.f32 "
        "{%0,%1,%2,%3}, {%4,%5,%6,%7}, {%8,%9}, {%0,%1,%2,%3};"
        : "+f"(c[0]), "+f"(c[1]), "+f"(c[2]), "+f"(c[3])
        : "r"(a[0]), "r"(a[1]), "r"(a[2]), "r"(a[3]),
          "r"(b[0]), "r"(b[1]));
}

// fp16 operand scratch: A (1024 x 4096) and W^T (1024 n x 4096 k), 8 MB each.
__device__ __half g_Ah[1024 * 4096];
__device__ __half g_Wth[1024 * 4096];

// ---------------------------------------------------------------------------
// Fused convert: blocks 0..4095 convert A slices -> g_Ah (fp16, k-contig);
// blocks 4096..8191 transpose+convert W -> g_Wth[n][k].
// ---------------------------------------------------------------------------
__global__ void convert_all(const float* __restrict__ memory,
                            const float* __restrict__ W)
{
    if (blockIdx.x < 4096) {
        const unsigned i = blockIdx.x * 256u + threadIdx.x;
        const unsigned m = i >> 10;
        const unsigned kq = (i & 1023u) << 2;
        const float* src = memory + ((size_t)(m >> 5) << 22) + 2097152u
                           + ((size_t)(m & 31) << 12) + kq;
        float4 v = *(const float4*)src;
        __half2* dst = (__half2*)(g_Ah + (size_t)m * 4096u + kq);
        dst[0] = __floats2half2_rn(v.x, v.y);
        dst[1] = __floats2half2_rn(v.z, v.w);
    } else {
        __shared__ __half tile[32][33];
        const int bb = blockIdx.x - 4096;
        const int nb = (bb & 31) * 32;
        const int kb = (bb >> 5) * 32;
        const int tx = threadIdx.x & 31;
        const int ty = threadIdx.x >> 5;     // 0..7
        for (int j = ty; j < 32; j += 8)
            tile[j][tx] = __float2half(W[(size_t)(kb + j) * 1024 + nb + tx]);
        __syncthreads();
        for (int j = ty; j < 32; j += 8)
            g_Wth[(size_t)(nb + j) * 4096 + kb + tx] = tile[tx][j];
    }
}

// ---------------------------------------------------------------------------
// fp16 GEMM. CTA tile 64x128, K-chunk 64 halves, 4-stage cp.async.
// Grid (8,16) = 128 CTAs, 256 threads / 8 warps.
// Warp map: ws = wid&3 spatial (wm=(ws&1)*32, wn=(ws>>1)*64, warp tile 32x64);
//           kh = wid>>2 K-half. End: kh=1 partials folded into kh=0 via smem.
// Smem rows padded to 72 halves (144B): ldmatrix rows hit banks (36r..36r+3)
// mod 32 -> conflict-free.
// Fragment loads via ldmatrix.m8n8.x4:
//   A (per mt): lanes 0-15 -> rows wm+mt*16+(l&15) @k; lanes 16-31 same rows
//               @k+8  => {a0,a1,a2,a3} in m16n8k16 order.
//   B (per np covering nt=2np,2np+1): lane row = wn+np*16+((l>>3)&1)*8+(l&7),
//               koff = k+((l>>4)<<3) => r0=bf[2np][0], r1=bf[2np+1][0],
//               r2=bf[2np][1], r3=bf[2np+1][1].
// ---------------------------------------------------------------------------
#define A_ST 72            // halves per A smem row
#define B_ST 72            // halves per B smem row
#define A_BYTES (64 * 144)                   // 9216
#define STAGE_BYTES (64 * 144 + 128 * 144)   // 27648
#define NSTAGE 4

__global__ void __launch_bounds__(256, 1)
gemm_f16(const float* __restrict__ bias, float* __restrict__ out)
{
    extern __shared__ __align__(16) char smem[];
    const int tid = threadIdx.x;
    const int wid = tid >> 5;
    const int lid = tid & 31;
    const int m0 = blockIdx.y * 64;
    const int n0 = blockIdx.x * 128;
    const int ws = wid & 3;
    const int kh = wid >> 2;
    const int wm = (ws & 1) * 32;
    const int wn = (ws >> 1) * 64;

    // Per-lane ldmatrix byte offsets (within a stage's A / B region).
    const int klane = ((lid >> 4) << 3);                 // 0 or 8 halves
    const int a_off0 = (wm + (lid & 15)) * A_ST + klane;          // mt=0
    const int a_off1 = (wm + 16 + (lid & 15)) * A_ST + klane;     // mt=1
    int b_off[4];
#pragma unroll
    for (int np = 0; np < 4; np++)
        b_off[np] = (wn + np * 16 + ((lid >> 3) & 1) * 8 + (lid & 7)) * B_ST
                    + klane;

    float acc[2][8][4];
#pragma unroll
    for (int i = 0; i < 2; i++)
#pragma unroll
        for (int j = 0; j < 8; j++)
#pragma unroll
            for (int k = 0; k < 4; k++) acc[i][j][k] = 0.0f;

    auto issue_stage = [&](int kc) {
        const int s = kc % NSTAGE;
        char* sa = smem + s * STAGE_BYTES;
        char* sb = sa + A_BYTES;
        const unsigned k0 = (unsigned)kc << 6;          // 64 halves per chunk
#pragma unroll
        for (int rep = 0; rep < 2; rep++) {
            const int i = tid + rep * 256;
            const int r = i >> 3, q = i & 7;
            const __half* src = g_Ah + (size_t)(m0 + r) * 4096u + k0 + (q << 3);
            CP_ASYNC16(smem_u32(sa + r * 144 + q * 16), src);
        }
#pragma unroll
        for (int rep = 0; rep < 4; rep++) {
            const int i = tid + rep * 256;
            const int r = i >> 3, q = i & 7;
            const __half* src = g_Wth + (size_t)(n0 + r) * 4096u + k0 + (q << 3);
            CP_ASYNC16(smem_u32(sb + r * 144 + q * 16), src);
        }
    };

    // Prologue: 3 stages in flight.
#pragma unroll
    for (int p = 0; p < NSTAGE - 1; ++p) {
        issue_stage(p);
        CP_ASYNC_COMMIT();
    }

    const uint32_t smem_base = smem_u32(smem);

    for (int kc = 0; kc < 64; ++kc) {
        CP_ASYNC_WAIT2();        // stage kc resident
        __syncthreads();         // everyone done with slot (kc-1)%4

        if (kc + NSTAGE - 1 < 64) {
            issue_stage(kc + NSTAGE - 1);   // writes slot (kc-1)%4 — safe
            CP_ASYNC_COMMIT();
        }

        const int s = kc % NSTAGE;
        const uint32_t saddr = smem_base + s * STAGE_BYTES;
        const uint32_t baddr = saddr + A_BYTES;

#pragma unroll
        for (int ks2 = 0; ks2 < 2; ++ks2) {
            const int k = (kh * 2 + ks2) << 4;     // k16 step offset in halves
            uint32_t af[2][4], bf[8][2];
            ldmatrix_x4(af[0][0], af[0][1], af[0][2], af[0][3],
                        saddr + (unsigned)(a_off0 + k) * 2u);
            ldmatrix_x4(af[1][0], af[1][1], af[1][2], af[1][3],
                        saddr + (unsigned)(a_off1 + k) * 2u);
#pragma unroll
            for (int np = 0; np < 4; np++)
                ldmatrix_x4(bf[2 * np][0], bf[2 * np + 1][0],
                            bf[2 * np][1], bf[2 * np + 1][1],
                            baddr + (unsigned)(b_off[np] + k) * 2u);
#pragma unroll
            for (int mt = 0; mt < 2; mt++)
#pragma unroll
                for (int nt = 0; nt < 8; nt++)
                    mma_f16_16n8k16(acc[mt][nt], af[mt], bf[nt]);
        }
    }
    CP_ASYNC_WAIT0();
    __syncthreads();   // compute done; smem reusable as reduction scratch

    // Intra-CTA K-split reduction: kh=1 warps dump partials, kh=0 warps fold.
    float* red = (float*)smem;          // 4 tiles x 2048 floats = 32KB
    if (kh == 1) {
#pragma unroll
        for (int mt = 0; mt < 2; mt++)
#pragma unroll
            for (int nt = 0; nt < 8; nt++)
#pragma unroll
                for (int c = 0; c < 4; c++) {
                    const int r = mt * 32 + nt * 4 + c;
                    red[ws * 2048 + r * 32 + lid] = acc[mt][nt][c];
                }
    }
    __syncthreads();
    if (kh == 0) {
#pragma unroll
        for (int mt = 0; mt < 2; mt++)
#pragma unroll
            for (int nt = 0; nt < 8; nt++)
#pragma unroll
                for (int c = 0; c < 4; c++) {
                    const int r = mt * 32 + nt * 4 + c;
                    acc[mt][nt][c] += red[ws * 2048 + r * 32 + lid];
                }

        // Epilogue: bias + direct float2 stores into the compression band.
#pragma unroll
        for (int mt = 0; mt < 2; mt++) {
#pragma unroll
            for (int nt = 0; nt < 8; nt++) {
                const int g = n0 + wn + nt * 8 + (lid & 3) * 2;
                const float2 bv = *(const float2*)(bias + g);
                const int m_lo = m0 + wm + mt * 16 + (lid >> 2);
                const int m_hi = m_lo + 8;
                float2 v0 = { acc[mt][nt][0] + bv.x, acc[mt][nt][1] + bv.y };
                float2 v1 = { acc[mt][nt][2] + bv.x, acc[mt][nt][3] + bv.y };
                *(float2*)(out + ((size_t)(m_lo >> 5) << 22)
                               + (size_t)(2016 + (m_lo & 31)) * 1024 + g) = v0;
                *(float2*)(out + ((size_t)(m_hi >> 5) << 22)
                               + (size_t)(2016 + (m_hi & 31)) * 1024 + g) = v1;
            }
        }
    }
}

// ---------------------------------------------------------------------------
// Copy kernel: pure shifted memcpy, float4-vectorized, grid-stride.
// ---------------------------------------------------------------------------
__global__ void copy_kernel(const float4* __restrict__ inputs,
                            const float4* __restrict__ memory,
                            float4* __restrict__ out)
{
    const unsigned total = 32u * 4096u * 256u;
    const unsigned stride = gridDim.x * blockDim.x;
    for (unsigned v = blockIdx.x * blockDim.x + threadIdx.x; v < total; v += stride) {
        unsigned f4 = v & 255u;
        unsigned rg = v >> 8;
        unsigned b  = rg >> 12;
        unsigned r  = rg & 4095u;
        float4 val;
        if (r < 2016u) {
            val = memory[(b << 20) + ((r + 32u) << 8) + f4];
        } else if (r < 2048u) {
            continue;  // compression band written by GEMM kernel
        } else if (r < 3968u) {
            val = memory[(b << 20) + ((r + 128u) << 8) + f4];
        } else {
            val = inputs[(b << 15) + ((r - 3968u) << 8) + f4];
        }
        out[v] = val;
    }
}

// ---------------------------------------------------------------------------
// Launch: convert -> GEMM -> copy (serial).
// ---------------------------------------------------------------------------
extern "C" void kernel_launch(void* const* d_in, const int* in_sizes, int n_in,
                              void* d_out, int out_size)
{
    const float* inputs = (const float*)d_in[0];   // (32, 128, 1024)
    const float* memory = (const float*)d_in[1];   // (32, 4096, 1024)
    const float* conv_w = (const float*)d_in[2];   // (4, 1024, 1024)
    const float* conv_b = (const float*)d_in[3];   // (1024,)
    float* out = (float*)d_out;                    // (32, 4096, 1024)

    cudaFuncSetAttribute(gemm_f16,
                         cudaFuncAttributeMaxDynamicSharedMemorySize,
                         STAGE_BYTES * NSTAGE);

    convert_all<<<8192, 256>>>(memory, conv_w);
    gemm_f16<<<dim3(8, 16), 256, STAGE_BYTES * NSTAGE>>>(conv_b, out);
    copy_kernel<<<8192, 256>>>((const float4*)inputs, (const float4*)memory,
                               (float4*)out);
}

// round 13
// speedup vs baseline: 1.1811x; 1.0231x over previous
#include <cuda_runtime.h>
#include <cuda_fp16.h>
#include <cstdint>

// ===========================================================================
// Problem: B=32, T=128, F=1024, CONV_UNITS=2048, SHORT_UNITS=2048, RATE=4
//   out[b, 0:2016,    :] = memory[b, 32:2048,   :]
//   out[b, 2016:2048, :] = compression (GEMM)
//   out[b, 2048:3968, :] = memory[b, 2176:4096, :]
//   out[b, 3968:4096, :] = inputs[b, :, :]
// GEMM: C(1024x1024) = A(1024x4096) @ W(4096x1024) + bias
//   A row m=(b*32+t): 4096 contiguous floats at memory + b*2^22 + 2097152 + t*4096
//
// fp16 m16n8k16 datapath + ldmatrix (R10/R11 wins). This round: convert_all
// was latency-bound (MLP=1, 18.5us @ 23% DRAM) -> give each thread 4
// independent loads (MLP=4) and each W block 4 k-tiles.
// ===========================================================================

#define CP_ASYNC16(dst, src) \
    asm volatile("cp.async.cg.shared.global [%0], [%1], 16;" \
                 :: "r"(dst), "l"(src) : "memory")
#define CP_ASYNC_COMMIT() asm volatile("cp.async.commit_group;" ::: "memory")
#define CP_ASYNC_WAIT2()  asm volatile("cp.async.wait_group 2;" ::: "memory")
#define CP_ASYNC_WAIT0()  asm volatile("cp.async.wait_group 0;" ::: "memory")

__device__ __forceinline__ uint32_t smem_u32(const void* p) {
    uint32_t a;
    asm("{ .reg .u64 t; cvta.to.shared.u64 t, %1; cvt.u32.u64 %0, t; }"
        : "=r"(a) : "l"(p));
    return a;
}

__device__ __forceinline__ void ldmatrix_x4(uint32_t& r0, uint32_t& r1,
                                            uint32_t& r2, uint32_t& r3,
                                            uint32_t addr) {
    asm volatile("ldmatrix.sync.aligned.m8n8.x4.shared.b16 {%0,%1,%2,%3}, [%4];"
                 : "=r"(r0), "=r"(r1), "=r"(r2), "=r"(r3) : "r"(addr));
}

__device__ __forceinline__ void mma_f16_16n8k16(float* c, const uint32_t* a,
                                                const uint32_t* b) {
    asm volatile(
        "mma.sync.aligned.m16n8k16.row.col.f32.f16.f16.f32 "
        "{%0,%1,%2,%3}, {%4,%5,%6,%7}, {%8,%9}, {%0,%1,%2,%3};"
        : "+f"(c[0]), "+f"(c[1]), "+f"(c[2]), "+f"(c[3])
        : "r"(a[0]), "r"(a[1]), "r"(a[2]), "r"(a[3]),
          "r"(b[0]), "r"(b[1]));
}

// fp16 operand scratch: A (1024 x 4096) and W^T (1024 n x 4096 k), 8 MB each.
__device__ __half g_Ah[1024 * 4096];
__device__ __half g_Wth[1024 * 4096];

// ---------------------------------------------------------------------------
// Fused convert, MLP-4.
// Blocks 0..1023: A -> g_Ah. Each thread: 4 independent float4 loads
//   (front-batched), 4 half2x2 stores. Thread i of block b handles float4
//   indices {b*1024 + t + 256*rep}, rep<4 -> A row = idx>>10, kq=(idx&1023)*4.
// Blocks 1024..2047: W transpose. Each block does 4 k-tiles (32n x 32k each)
//   with loads for all 4 tiles issued per j-iteration (MLP 4).
// ---------------------------------------------------------------------------
__global__ void convert_all(const float* __restrict__ memory,
                            const float* __restrict__ W)
{
    if (blockIdx.x < 1024) {
        const unsigned base = blockIdx.x * 1024u + threadIdx.x;
        float4 v[4];
#pragma unroll
        for (int rep = 0; rep < 4; rep++) {
            const unsigned i = base + rep * 256u;
            const unsigned m = i >> 10;
            const unsigned kq = (i & 1023u) << 2;
            const float* src = memory + ((size_t)(m >> 5) << 22) + 2097152u
                               + ((size_t)(m & 31) << 12) + kq;
            v[rep] = *(const float4*)src;
        }
#pragma unroll
        for (int rep = 0; rep < 4; rep++) {
            const unsigned i = base + rep * 256u;
            const unsigned m = i >> 10;
            const unsigned kq = (i & 1023u) << 2;
            __half2* dst = (__half2*)(g_Ah + (size_t)m * 4096u + kq);
            dst[0] = __floats2half2_rn(v[rep].x, v[rep].y);
            dst[1] = __floats2half2_rn(v[rep].z, v[rep].w);
        }
    } else {
        __shared__ __half tile[4][32][33];
        const int bb = blockIdx.x - 1024;         // 0..1023
        const int nb = (bb & 31) * 32;            // n base
        const int kb0 = (bb >> 5) * 128;          // k base (4 tiles of 32)
        const int tx = threadIdx.x & 31;
        const int ty = threadIdx.x >> 5;          // 0..7
        for (int j = ty; j < 32; j += 8) {
            float f[4];
#pragma unroll
            for (int t = 0; t < 4; t++)
                f[t] = W[(size_t)(kb0 + t * 32 + j) * 1024 + nb + tx];
#pragma unroll
            for (int t = 0; t < 4; t++)
                tile[t][j][tx] = __float2half(f[t]);
        }
        __syncthreads();
        for (int j = ty; j < 32; j += 8) {
#pragma unroll
            for (int t = 0; t < 4; t++)
                g_Wth[(size_t)(nb + j) * 4096 + kb0 + t * 32 + tx] =
                    tile[t][tx][j];
        }
    }
}

// ---------------------------------------------------------------------------
// fp16 GEMM. CTA tile 64x128, K-chunk 64 halves, 4-stage cp.async.
// Grid (8,16) = 128 CTAs, 256 threads / 8 warps.
// Warp map: ws = wid&3 spatial (wm=(ws&1)*32, wn=(ws>>1)*64, warp tile 32x64);
//           kh = wid>>2 K-half. End: kh=1 partials folded into kh=0 via smem.
// Smem rows padded to 72 halves (144B) -> ldmatrix conflict-free.
// ---------------------------------------------------------------------------
#define A_ST 72            // halves per A smem row
#define B_ST 72            // halves per B smem row
#define A_BYTES (64 * 144)                   // 9216
#define STAGE_BYTES (64 * 144 + 128 * 144)   // 27648
#define NSTAGE 4

__global__ void __launch_bounds__(256, 1)
gemm_f16(const float* __restrict__ bias, float* __restrict__ out)
{
    extern __shared__ __align__(16) char smem[];
    const int tid = threadIdx.x;
    const int wid = tid >> 5;
    const int lid = tid & 31;
    const int m0 = blockIdx.y * 64;
    const int n0 = blockIdx.x * 128;
    const int ws = wid & 3;
    const int kh = wid >> 2;
    const int wm = (ws & 1) * 32;
    const int wn = (ws >> 1) * 64;

    // Per-lane ldmatrix offsets (halves, within a stage's A / B region).
    const int klane = ((lid >> 4) << 3);                 // 0 or 8 halves
    const int a_off0 = (wm + (lid & 15)) * A_ST + klane;          // mt=0
    const int a_off1 = (wm + 16 + (lid & 15)) * A_ST + klane;     // mt=1
    int b_off[4];
#pragma unroll
    for (int np = 0; np < 4; np++)
        b_off[np] = (wn + np * 16 + ((lid >> 3) & 1) * 8 + (lid & 7)) * B_ST
                    + klane;

    float acc[2][8][4];
#pragma unroll
    for (int i = 0; i < 2; i++)
#pragma unroll
        for (int j = 0; j < 8; j++)
#pragma unroll
            for (int k = 0; k < 4; k++) acc[i][j][k] = 0.0f;

    auto issue_stage = [&](int kc) {
        const int s = kc % NSTAGE;
        char* sa = smem + s * STAGE_BYTES;
        char* sb = sa + A_BYTES;
        const unsigned k0 = (unsigned)kc << 6;          // 64 halves per chunk
#pragma unroll
        for (int rep = 0; rep < 2; rep++) {
            const int i = tid + rep * 256;
            const int r = i >> 3, q = i & 7;
            const __half* src = g_Ah + (size_t)(m0 + r) * 4096u + k0 + (q << 3);
            CP_ASYNC16(smem_u32(sa + r * 144 + q * 16), src);
        }
#pragma unroll
        for (int rep = 0; rep < 4; rep++) {
            const int i = tid + rep * 256;
            const int r = i >> 3, q = i & 7;
            const __half* src = g_Wth + (size_t)(n0 + r) * 4096u + k0 + (q << 3);
            CP_ASYNC16(smem_u32(sb + r * 144 + q * 16), src);
        }
    };

    // Prologue: 3 stages in flight.
#pragma unroll
    for (int p = 0; p < NSTAGE - 1; ++p) {
        issue_stage(p);
        CP_ASYNC_COMMIT();
    }

    const uint32_t smem_base = smem_u32(smem);

    for (int kc = 0; kc < 64; ++kc) {
        CP_ASYNC_WAIT2();        // stage kc resident
        __syncthreads();         // everyone done with slot (kc-1)%4

        if (kc + NSTAGE - 1 < 64) {
            issue_stage(kc + NSTAGE - 1);   // writes slot (kc-1)%4 — safe
            CP_ASYNC_COMMIT();
        }

        const int s = kc % NSTAGE;
        const uint32_t saddr = smem_base + s * STAGE_BYTES;
        const uint32_t baddr = saddr + A_BYTES;

#pragma unroll
        for (int ks2 = 0; ks2 < 2; ++ks2) {
            const int k = (kh * 2 + ks2) << 4;     // k16 step offset in halves
            uint32_t af[2][4], bf[8][2];
            ldmatrix_x4(af[0][0], af[0][1], af[0][2], af[0][3],
                        saddr + (unsigned)(a_off0 + k) * 2u);
            ldmatrix_x4(af[1][0], af[1][1], af[1][2], af[1][3],
                        saddr + (unsigned)(a_off1 + k) * 2u);
#pragma unroll
            for (int np = 0; np < 4; np++)
                ldmatrix_x4(bf[2 * np][0], bf[2 * np + 1][0],
                            bf[2 * np][1], bf[2 * np + 1][1],
                            baddr + (unsigned)(b_off[np] + k) * 2u);
#pragma unroll
            for (int mt = 0; mt < 2; mt++)
#pragma unroll
                for (int nt = 0; nt < 8; nt++)
                    mma_f16_16n8k16(acc[mt][nt], af[mt], bf[nt]);
        }
    }
    CP_ASYNC_WAIT0();
    __syncthreads();   // compute done; smem reusable as reduction scratch

    // Intra-CTA K-split reduction: kh=1 warps dump partials, kh=0 warps fold.
    float* red = (float*)smem;          // 4 tiles x 2048 floats = 32KB
    if (kh == 1) {
#pragma unroll
        for (int mt = 0; mt < 2; mt++)
#pragma unroll
            for (int nt = 0; nt < 8; nt++)
#pragma unroll
                for (int c = 0; c < 4; c++) {
                    const int r = mt * 32 + nt * 4 + c;
                    red[ws * 2048 + r * 32 + lid] = acc[mt][nt][c];
                }
    }
    __syncthreads();
    if (kh == 0) {
#pragma unroll
        for (int mt = 0; mt < 2; mt++)
#pragma unroll
            for (int nt = 0; nt < 8; nt++)
#pragma unroll
                for (int c = 0; c < 4; c++) {
                    const int r = mt * 32 + nt * 4 + c;
                    acc[mt][nt][c] += red[ws * 2048 + r * 32 + lid];
                }

        // Epilogue: bias + direct float2 stores into the compression band.
#pragma unroll
        for (int mt = 0; mt < 2; mt++) {
#pragma unroll
            for (int nt = 0; nt < 8; nt++) {
                const int g = n0 + wn + nt * 8 + (lid & 3) * 2;
                const float2 bv = *(const float2*)(bias + g);
                const int m_lo = m0 + wm + mt * 16 + (lid >> 2);
                const int m_hi = m_lo + 8;
                float2 v0 = { acc[mt][nt][0] + bv.x, acc[mt][nt][1] + bv.y };
                float2 v1 = { acc[mt][nt][2] + bv.x, acc[mt][nt][3] + bv.y };
                *(float2*)(out + ((size_t)(m_lo >> 5) << 22)
                               + (size_t)(2016 + (m_lo & 31)) * 1024 + g) = v0;
                *(float2*)(out + ((size_t)(m_hi >> 5) << 22)
                               + (size_t)(2016 + (m_hi & 31)) * 1024 + g) = v1;
            }
        }
    }
}

// ---------------------------------------------------------------------------
// Copy kernel: pure shifted memcpy, float4-vectorized, grid-stride.
// ---------------------------------------------------------------------------
__global__ void copy_kernel(const float4* __restrict__ inputs,
                            const float4* __restrict__ memory,
                            float4* __restrict__ out)
{
    const unsigned total = 32u * 4096u * 256u;
    const unsigned stride = gridDim.x * blockDim.x;
    for (unsigned v = blockIdx.x * blockDim.x + threadIdx.x; v < total; v += stride) {
        unsigned f4 = v & 255u;
        unsigned rg = v >> 8;
        unsigned b  = rg >> 12;
        unsigned r  = rg & 4095u;
        float4 val;
        if (r < 2016u) {
            val = memory[(b << 20) + ((r + 32u) << 8) + f4];
        } else if (r < 2048u) {
            continue;  // compression band written by GEMM kernel
        } else if (r < 3968u) {
            val = memory[(b << 20) + ((r + 128u) << 8) + f4];
        } else {
            val = inputs[(b << 15) + ((r - 3968u) << 8) + f4];
        }
        out[v] = val;
    }
}

// ---------------------------------------------------------------------------
// Launch: convert -> GEMM -> copy (serial).
// ---------------------------------------------------------------------------
extern "C" void kernel_launch(void* const* d_in, const int* in_sizes, int n_in,
                              void* d_out, int out_size)
{
    const float* inputs = (const float*)d_in[0];   // (32, 128, 1024)
    const float* memory = (const float*)d_in[1];   // (32, 4096, 1024)
    const float* conv_w = (const float*)d_in[2];   // (4, 1024, 1024)
    const float* conv_b = (const float*)d_in[3];   // (1024,)
    float* out = (float*)d_out;                    // (32, 4096, 1024)

    cudaFuncSetAttribute(gemm_f16,
                         cudaFuncAttributeMaxDynamicSharedMemorySize,
                         STAGE_BYTES * NSTAGE);

    convert_all<<<2048, 256>>>(memory, conv_w);
    gemm_f16<<<dim3(8, 16), 256, STAGE_BYTES * NSTAGE>>>(conv_b, out);
    copy_kernel<<<8192, 256>>>((const float4*)inputs, (const float4*)memory,
                               (float4*)out);
}

// round 15
// speedup vs baseline: 1.1984x; 1.0146x over previous
#include <cuda_runtime.h>
#include <cuda_fp16.h>
#include <cstdint>

// ===========================================================================
// Problem: B=32, T=128, F=1024, CONV_UNITS=2048, SHORT_UNITS=2048, RATE=4
//   out[b, 0:2016,    :] = memory[b, 32:2048,   :]
//   out[b, 2016:2048, :] = compression (GEMM)
//   out[b, 2048:3968, :] = memory[b, 2176:4096, :]
//   out[b, 3968:4096, :] = inputs[b, :, :]
// GEMM: C(1024x1024) = A(1024x4096) @ W(4096x1024) + bias
//   A row m=(b*32+t): 4096 contiguous floats at memory + b*2^22 + 2097152 + t*4096
//
// fp16 m16n8k16 + ldmatrix + MLP-4 converts (R10-R12 wins). R14 was an infra
// failure; resubmitting the 512-thread / 16-warp GEMM (2x2 spatial x 4-way
// per-chunk K-split) to interleave HMMA issue across 4 warps/SMSP.
// ===========================================================================

#define CP_ASYNC16(dst, src) \
    asm volatile("cp.async.cg.shared.global [%0], [%1], 16;" \
                 :: "r"(dst), "l"(src) : "memory")
#define CP_ASYNC_COMMIT() asm volatile("cp.async.commit_group;" ::: "memory")
#define CP_ASYNC_WAIT2()  asm volatile("cp.async.wait_group 2;" ::: "memory")
#define CP_ASYNC_WAIT0()  asm volatile("cp.async.wait_group 0;" ::: "memory")

__device__ __forceinline__ uint32_t smem_u32(const void* p) {
    uint32_t a;
    asm("{ .reg .u64 t; cvta.to.shared.u64 t, %1; cvt.u32.u64 %0, t; }"
        : "=r"(a) : "l"(p));
    return a;
}

__device__ __forceinline__ void ldmatrix_x4(uint32_t& r0, uint32_t& r1,
                                            uint32_t& r2, uint32_t& r3,
                                            uint32_t addr) {
    asm volatile("ldmatrix.sync.aligned.m8n8.x4.shared.b16 {%0,%1,%2,%3}, [%4];"
                 : "=r"(r0), "=r"(r1), "=r"(r2), "=r"(r3) : "r"(addr));
}

__device__ __forceinline__ void mma_f16_16n8k16(float* c, const uint32_t* a,
                                                const uint32_t* b) {
    asm volatile(
        "mma.sync.aligned.m16n8k16.row.col.f32.f16.f16.f32 "
        "{%0,%1,%2,%3}, {%4,%5,%6,%7}, {%8,%9}, {%0,%1,%2,%3};"
        : "+f"(c[0]), "+f"(c[1]), "+f"(c[2]), "+f"(c[3])
        : "r"(a[0]), "r"(a[1]), "r"(a[2]), "r"(a[3]),
          "r"(b[0]), "r"(b[1]));
}

// fp16 operand scratch: A (1024 x 4096) and W^T (1024 n x 4096 k), 8 MB each.
__device__ __half g_Ah[1024 * 4096];
__device__ __half g_Wth[1024 * 4096];

// ---------------------------------------------------------------------------
// Fused convert, MLP-4 (R12 form, unchanged).
// ---------------------------------------------------------------------------
__global__ void convert_all(const float* __restrict__ memory,
                            const float* __restrict__ W)
{
    if (blockIdx.x < 1024) {
        const unsigned base = blockIdx.x * 1024u + threadIdx.x;
        float4 v[4];
#pragma unroll
        for (int rep = 0; rep < 4; rep++) {
            const unsigned i = base + rep * 256u;
            const unsigned m = i >> 10;
            const unsigned kq = (i & 1023u) << 2;
            const float* src = memory + ((size_t)(m >> 5) << 22) + 2097152u
                               + ((size_t)(m & 31) << 12) + kq;
            v[rep] = *(const float4*)src;
        }
#pragma unroll
        for (int rep = 0; rep < 4; rep++) {
            const unsigned i = base + rep * 256u;
            const unsigned m = i >> 10;
            const unsigned kq = (i & 1023u) << 2;
            __half2* dst = (__half2*)(g_Ah + (size_t)m * 4096u + kq);
            dst[0] = __floats2half2_rn(v[rep].x, v[rep].y);
            dst[1] = __floats2half2_rn(v[rep].z, v[rep].w);
        }
    } else {
        __shared__ __half tile[4][32][33];
        const int bb = blockIdx.x - 1024;         // 0..1023
        const int nb = (bb & 31) * 32;            // n base
        const int kb0 = (bb >> 5) * 128;          // k base (4 tiles of 32)
        const int tx = threadIdx.x & 31;
        const int ty = threadIdx.x >> 5;          // 0..7
        for (int j = ty; j < 32; j += 8) {
            float f[4];
#pragma unroll
            for (int t = 0; t < 4; t++)
                f[t] = W[(size_t)(kb0 + t * 32 + j) * 1024 + nb + tx];
#pragma unroll
            for (int t = 0; t < 4; t++)
                tile[t][j][tx] = __float2half(f[t]);
        }
        __syncthreads();
        for (int j = ty; j < 32; j += 8) {
#pragma unroll
            for (int t = 0; t < 4; t++)
                g_Wth[(size_t)(nb + j) * 4096 + kb0 + t * 32 + tx] =
                    tile[t][tx][j];
        }
    }
}

// ---------------------------------------------------------------------------
// fp16 GEMM. CTA tile 64x128, K-chunk 64 halves, 4-stage cp.async.
// Grid (8,16) = 128 CTAs, 512 threads / 16 warps.
// Warp map: ws = wid&3 spatial (wm=(ws&1)*32, wn=(ws>>1)*64, warp tile 32x64);
//           kh = wid>>2 in 0..3: warp handles k16-step kh of each chunk.
// End: kh=1..3 partial layers dumped to smem (96KB), kh=0 folds + epilogue.
// Smem rows padded to 72 halves (144B) -> ldmatrix conflict-free.
// ---------------------------------------------------------------------------
#define A_ST 72            // halves per A smem row
#define B_ST 72            // halves per B smem row
#define A_BYTES (64 * 144)                   // 9216
#define STAGE_BYTES (64 * 144 + 128 * 144)   // 27648
#define NSTAGE 4
#define NTHREADS 512

__global__ void __launch_bounds__(NTHREADS, 1)
gemm_f16(const float* __restrict__ bias, float* __restrict__ out)
{
    extern __shared__ __align__(16) char smem[];
    const int tid = threadIdx.x;
    const int wid = tid >> 5;
    const int lid = tid & 31;
    const int m0 = blockIdx.y * 64;
    const int n0 = blockIdx.x * 128;
    const int ws = wid & 3;
    const int kh = wid >> 2;            // 0..3
    const int wm = (ws & 1) * 32;
    const int wn = (ws >> 1) * 64;

    // Per-lane ldmatrix offsets (halves, within a stage's region), kh folded in.
    const int klane = ((lid >> 4) << 3) + kh * 16;       // k16-step kh
    const int a_off0 = (wm + (lid & 15)) * A_ST + klane;          // mt=0
    const int a_off1 = (wm + 16 + (lid & 15)) * A_ST + klane;     // mt=1
    int b_off[4];
#pragma unroll
    for (int np = 0; np < 4; np++)
        b_off[np] = (wn + np * 16 + ((lid >> 3) & 1) * 8 + (lid & 7)) * B_ST
                    + klane;

    float acc[2][8][4];
#pragma unroll
    for (int i = 0; i < 2; i++)
#pragma unroll
        for (int j = 0; j < 8; j++)
#pragma unroll
            for (int k = 0; k < 4; k++) acc[i][j][k] = 0.0f;

    auto issue_stage = [&](int kc) {
        const int s = kc % NSTAGE;
        char* sa = smem + s * STAGE_BYTES;
        char* sb = sa + A_BYTES;
        const unsigned k0 = (unsigned)kc << 6;          // 64 halves per chunk
        // A: 512 transfers -> 1 per thread.
        {
            const int r = tid >> 3, q = tid & 7;
            const __half* src = g_Ah + (size_t)(m0 + r) * 4096u + k0 + (q << 3);
            CP_ASYNC16(smem_u32(sa + r * 144 + q * 16), src);
        }
        // B: 1024 transfers -> 2 per thread.
#pragma unroll
        for (int rep = 0; rep < 2; rep++) {
            const int i = tid + rep * NTHREADS;
            const int r = i >> 3, q = i & 7;
            const __half* src = g_Wth + (size_t)(n0 + r) * 4096u + k0 + (q << 3);
            CP_ASYNC16(smem_u32(sb + r * 144 + q * 16), src);
        }
    };

    // Prologue: 3 stages in flight.
#pragma unroll
    for (int p = 0; p < NSTAGE - 1; ++p) {
        issue_stage(p);
        CP_ASYNC_COMMIT();
    }

    const uint32_t smem_base = smem_u32(smem);

    for (int kc = 0; kc < 64; ++kc) {
        CP_ASYNC_WAIT2();        // stage kc resident
        __syncthreads();         // everyone done with slot (kc-1)%4

        if (kc + NSTAGE - 1 < 64) {
            issue_stage(kc + NSTAGE - 1);   // writes slot (kc-1)%4 — safe
            CP_ASYNC_COMMIT();
        }

        const int s = kc % NSTAGE;
        const uint32_t saddr = smem_base + s * STAGE_BYTES;
        const uint32_t baddr = saddr + A_BYTES;

        uint32_t af[2][4], bf[8][2];
        ldmatrix_x4(af[0][0], af[0][1], af[0][2], af[0][3],
                    saddr + (unsigned)a_off0 * 2u);
        ldmatrix_x4(af[1][0], af[1][1], af[1][2], af[1][3],
                    saddr + (unsigned)a_off1 * 2u);
#pragma unroll
        for (int np = 0; np < 4; np++)
            ldmatrix_x4(bf[2 * np][0], bf[2 * np + 1][0],
                        bf[2 * np][1], bf[2 * np + 1][1],
                        baddr + (unsigned)b_off[np] * 2u);
#pragma unroll
        for (int mt = 0; mt < 2; mt++)
#pragma unroll
            for (int nt = 0; nt < 8; nt++)
                mma_f16_16n8k16(acc[mt][nt], af[mt], bf[nt]);
    }
    CP_ASYNC_WAIT0();
    __syncthreads();   // compute done; smem reusable as reduction scratch

    // K-split reduction: kh=1..3 dump partial layers, kh=0 folds.
    float* red = (float*)smem;    // 3 layers x 4 ws x 2048 floats = 96KB <= 110KB
    if (kh != 0) {
#pragma unroll
        for (int mt = 0; mt < 2; mt++)
#pragma unroll
            for (int nt = 0; nt < 8; nt++)
#pragma unroll
                for (int c = 0; c < 4; c++) {
                    const int r = mt * 32 + nt * 4 + c;
                    red[((kh - 1) * 4 + ws) * 2048 + r * 32 + lid] =
                        acc[mt][nt][c];
                }
    }
    __syncthreads();
    if (kh == 0) {
#pragma unroll
        for (int mt = 0; mt < 2; mt++)
#pragma unroll
            for (int nt = 0; nt < 8; nt++)
#pragma unroll
                for (int c = 0; c < 4; c++) {
                    const int r = mt * 32 + nt * 4 + c;
                    const int idx = ws * 2048 + r * 32 + lid;
                    acc[mt][nt][c] += red[idx]
                                    + red[4 * 2048 + idx]
                                    + red[8 * 2048 + idx];
                }

        // Epilogue: bias + direct float2 stores into the compression band.
#pragma unroll
        for (int mt = 0; mt < 2; mt++) {
#pragma unroll
            for (int nt = 0; nt < 8; nt++) {
                const int g = n0 + wn + nt * 8 + (lid & 3) * 2;
                const float2 bv = *(const float2*)(bias + g);
                const int m_lo = m0 + wm + mt * 16 + (lid >> 2);
                const int m_hi = m_lo + 8;
                float2 v0 = { acc[mt][nt][0] + bv.x, acc[mt][nt][1] + bv.y };
                float2 v1 = { acc[mt][nt][2] + bv.x, acc[mt][nt][3] + bv.y };
                *(float2*)(out + ((size_t)(m_lo >> 5) << 22)
                               + (size_t)(2016 + (m_lo & 31)) * 1024 + g) = v0;
                *(float2*)(out + ((size_t)(m_hi >> 5) << 22)
                               + (size_t)(2016 + (m_hi & 31)) * 1024 + g) = v1;
            }
        }
    }
}

// ---------------------------------------------------------------------------
// Copy kernel: pure shifted memcpy, float4-vectorized, grid-stride.
// ---------------------------------------------------------------------------
__global__ void copy_kernel(const float4* __restrict__ inputs,
                            const float4* __restrict__ memory,
                            float4* __restrict__ out)
{
    const unsigned total = 32u * 4096u * 256u;
    const unsigned stride = gridDim.x * blockDim.x;
    for (unsigned v = blockIdx.x * blockDim.x + threadIdx.x; v < total; v += stride) {
        unsigned f4 = v & 255u;
        unsigned rg = v >> 8;
        unsigned b  = rg >> 12;
        unsigned r  = rg & 4095u;
        float4 val;
        if (r < 2016u) {
            val = memory[(b << 20) + ((r + 32u) << 8) + f4];
        } else if (r < 2048u) {
            continue;  // compression band written by GEMM kernel
        } else if (r < 3968u) {
            val = memory[(b << 20) + ((r + 128u) << 8) + f4];
        } else {
            val = inputs[(b << 15) + ((r - 3968u) << 8) + f4];
        }
        out[v] = val;
    }
}

// ---------------------------------------------------------------------------
// Launch: convert -> GEMM -> copy (serial).
// ---------------------------------------------------------------------------
extern "C" void kernel_launch(void* const* d_in, const int* in_sizes, int n_in,
                              void* d_out, int out_size)
{
    const float* inputs = (const float*)d_in[0];   // (32, 128, 1024)
    const float* memory = (const float*)d_in[1];   // (32, 4096, 1024)
    const float* conv_w = (const float*)d_in[2];   // (4, 1024, 1024)
    const float* conv_b = (const float*)d_in[3];   // (1024,)
    float* out = (float*)d_out;                    // (32, 4096, 1024)

    cudaFuncSetAttribute(gemm_f16,
                         cudaFuncAttributeMaxDynamicSharedMemorySize,
                         STAGE_BYTES * NSTAGE);

    convert_all<<<2048, 256>>>(memory, conv_w);
    gemm_f16<<<dim3(8, 16), NTHREADS, STAGE_BYTES * NSTAGE>>>(conv_b, out);
    copy_kernel<<<8192, 256>>>((const float4*)inputs, (const float4*)memory,
                               (float4*)out);
}

// round 16
// speedup vs baseline: 1.1998x; 1.0012x over previous
#include <cuda_runtime.h>
#include <cuda_fp16.h>
#include <cstdint>

// ===========================================================================
// Problem: B=32, T=128, F=1024, CONV_UNITS=2048, SHORT_UNITS=2048, RATE=4
//   out[b, 0:2016,    :] = memory[b, 32:2048,   :]
//   out[b, 2016:2048, :] = compression (GEMM)
//   out[b, 2048:3968, :] = memory[b, 2176:4096, :]
//   out[b, 3968:4096, :] = inputs[b, :, :]
// GEMM: C(1024x1024) = A(1024x4096) @ W(4096x1024) + bias
//   A row m=(b*32+t): 4096 contiguous floats at memory + b*2^22 + 2097152 + t*4096
//
// fp16 m16n8k16 + ldmatrix, 16-warp GEMM (R15, ~43us, near HMMA floor).
// This round: convert_all store path vectorized -- A writes 2x STG.128
// (was 8x STG.32), W-transpose repacks via smem and writes STG.128
// (was 32x STG.U16 per thread). Loads keep MLP=4.
// ===========================================================================

#define CP_ASYNC16(dst, src) \
    asm volatile("cp.async.cg.shared.global [%0], [%1], 16;" \
                 :: "r"(dst), "l"(src) : "memory")
#define CP_ASYNC_COMMIT() asm volatile("cp.async.commit_group;" ::: "memory")
#define CP_ASYNC_WAIT2()  asm volatile("cp.async.wait_group 2;" ::: "memory")
#define CP_ASYNC_WAIT0()  asm volatile("cp.async.wait_group 0;" ::: "memory")

__device__ __forceinline__ uint32_t smem_u32(const void* p) {
    uint32_t a;
    asm("{ .reg .u64 t; cvta.to.shared.u64 t, %1; cvt.u32.u64 %0, t; }"
        : "=r"(a) : "l"(p));
    return a;
}

__device__ __forceinline__ void ldmatrix_x4(uint32_t& r0, uint32_t& r1,
                                            uint32_t& r2, uint32_t& r3,
                                            uint32_t addr) {
    asm volatile("ldmatrix.sync.aligned.m8n8.x4.shared.b16 {%0,%1,%2,%3}, [%4];"
                 : "=r"(r0), "=r"(r1), "=r"(r2), "=r"(r3) : "r"(addr));
}

__device__ __forceinline__ void mma_f16_16n8k16(float* c, const uint32_t* a,
                                                const uint32_t* b) {
    asm volatile(
        "mma.sync.aligned.m16n8k16.row.col.f32.f16.f16.f32 "
        "{%0,%1,%2,%3}, {%4,%5,%6,%7}, {%8,%9}, {%0,%1,%2,%3};"
        : "+f"(c[0]), "+f"(c[1]), "+f"(c[2]), "+f"(c[3])
        : "r"(a[0]), "r"(a[1]), "r"(a[2]), "r"(a[3]),
          "r"(b[0]), "r"(b[1]));
}

__device__ __forceinline__ uint32_t pack_half2(float a, float b) {
    __half2 h = __floats2half2_rn(a, b);
    return *(uint32_t*)&h;
}
__device__ __forceinline__ uint32_t pack2h(__half a, __half b) {
    return (uint32_t)__half_as_ushort(a) | ((uint32_t)__half_as_ushort(b) << 16);
}

// fp16 operand scratch: A (1024 x 4096) and W^T (1024 n x 4096 k), 8 MB each.
__device__ __half g_Ah[1024 * 4096];
__device__ __half g_Wth[1024 * 4096];

// ---------------------------------------------------------------------------
// Fused convert, MLP-4 loads + vectorized STG.128 stores.
// Blocks 0..1023: A -> g_Ah. Each thread: 2 tasks; task = 2 consecutive
//   float4 (32B fp32) -> 1 uint4 (16B fp16) store. 4 loads front-batched.
// Blocks 1024..2047: W transpose. Load 4 k-tiles into smem (as before), then
//   store phase: 512 tasks (32 n-rows x 16 k-segments of 8 halves); each
//   thread packs 8 halves from smem -> 1 STG.128. 2 tasks per thread.
// ---------------------------------------------------------------------------
__global__ void convert_all(const float* __restrict__ memory,
                            const float* __restrict__ W)
{
    if (blockIdx.x < 1024) {
        const unsigned pbase = blockIdx.x * 512u + threadIdx.x;   // pair index
        float4 v[4];
#pragma unroll
        for (int rep = 0; rep < 2; rep++) {
            const unsigned p = pbase + rep * 256u;
            const unsigned i0 = p << 1;                 // even float4 idx
            const unsigned m = i0 >> 10;
            const unsigned kq = (i0 & 1023u) << 2;      // multiple of 8
            const float* src = memory + ((size_t)(m >> 5) << 22) + 2097152u
                               + ((size_t)(m & 31) << 12) + kq;
            v[2 * rep]     = *(const float4*)src;
            v[2 * rep + 1] = *(const float4*)(src + 4);
        }
#pragma unroll
        for (int rep = 0; rep < 2; rep++) {
            const unsigned p = pbase + rep * 256u;
            const unsigned i0 = p << 1;
            const unsigned m = i0 >> 10;
            const unsigned kq = (i0 & 1023u) << 2;
            const float4 a = v[2 * rep], b = v[2 * rep + 1];
            uint4 u;
            u.x = pack_half2(a.x, a.y);
            u.y = pack_half2(a.z, a.w);
            u.z = pack_half2(b.x, b.y);
            u.w = pack_half2(b.z, b.w);
            *(uint4*)(g_Ah + (size_t)m * 4096u + kq) = u;
        }
    } else {
        __shared__ __half tile[4][32][33];
        const int bb = blockIdx.x - 1024;         // 0..1023
        const int nb = (bb & 31) * 32;            // n base
        const int kb0 = (bb >> 5) * 128;          // k base (4 tiles of 32)
        const int tx = threadIdx.x & 31;
        const int ty = threadIdx.x >> 5;          // 0..7
        for (int j = ty; j < 32; j += 8) {
            float f[4];
#pragma unroll
            for (int t = 0; t < 4; t++)
                f[t] = W[(size_t)(kb0 + t * 32 + j) * 1024 + nb + tx];
#pragma unroll
            for (int t = 0; t < 4; t++)
                tile[t][j][tx] = __float2half(f[t]);
        }
        __syncthreads();
        // Store phase: 32 n-rows x 16 segments of 8 k-halves = 512 tasks.
#pragma unroll
        for (int rep = 0; rep < 2; rep++) {
            const int i = threadIdx.x + rep * 256;
            const int n_l = i >> 4;               // 0..31
            const int seg = i & 15;               // 0..15
            const int t = seg >> 2;               // tile 0..3
            const int kk = (seg & 3) * 8;         // 0,8,16,24
            __half h[8];
#pragma unroll
            for (int hh = 0; hh < 8; hh++)
                h[hh] = tile[t][kk + hh][n_l];
            uint4 u;
            u.x = pack2h(h[0], h[1]);
            u.y = pack2h(h[2], h[3]);
            u.z = pack2h(h[4], h[5]);
            u.w = pack2h(h[6], h[7]);
            *(uint4*)(g_Wth + (size_t)(nb + n_l) * 4096 + kb0 + seg * 8) = u;
        }
    }
}

// ---------------------------------------------------------------------------
// fp16 GEMM (R15 form, unchanged). CTA tile 64x128, K-chunk 64 halves,
// 4-stage cp.async. Grid (8,16) = 128 CTAs, 512 threads / 16 warps.
// Warp map: ws = wid&3 spatial (32x64 tile); kh = wid>>2 per-chunk K-split.
// ---------------------------------------------------------------------------
#define A_ST 72
#define B_ST 72
#define A_BYTES (64 * 144)
#define STAGE_BYTES (64 * 144 + 128 * 144)
#define NSTAGE 4
#define NTHREADS 512

__global__ void __launch_bounds__(NTHREADS, 1)
gemm_f16(const float* __restrict__ bias, float* __restrict__ out)
{
    extern __shared__ __align__(16) char smem[];
    const int tid = threadIdx.x;
    const int wid = tid >> 5;
    const int lid = tid & 31;
    const int m0 = blockIdx.y * 64;
    const int n0 = blockIdx.x * 128;
    const int ws = wid & 3;
    const int kh = wid >> 2;            // 0..3
    const int wm = (ws & 1) * 32;
    const int wn = (ws >> 1) * 64;

    const int klane = ((lid >> 4) << 3) + kh * 16;
    const int a_off0 = (wm + (lid & 15)) * A_ST + klane;
    const int a_off1 = (wm + 16 + (lid & 15)) * A_ST + klane;
    int b_off[4];
#pragma unroll
    for (int np = 0; np < 4; np++)
        b_off[np] = (wn + np * 16 + ((lid >> 3) & 1) * 8 + (lid & 7)) * B_ST
                    + klane;

    float acc[2][8][4];
#pragma unroll
    for (int i = 0; i < 2; i++)
#pragma unroll
        for (int j = 0; j < 8; j++)
#pragma unroll
            for (int k = 0; k < 4; k++) acc[i][j][k] = 0.0f;

    auto issue_stage = [&](int kc) {
        const int s = kc % NSTAGE;
        char* sa = smem + s * STAGE_BYTES;
        char* sb = sa + A_BYTES;
        const unsigned k0 = (unsigned)kc << 6;
        {
            const int r = tid >> 3, q = tid & 7;
            const __half* src = g_Ah + (size_t)(m0 + r) * 4096u + k0 + (q << 3);
            CP_ASYNC16(smem_u32(sa + r * 144 + q * 16), src);
        }
#pragma unroll
        for (int rep = 0; rep < 2; rep++) {
            const int i = tid + rep * NTHREADS;
            const int r = i >> 3, q = i & 7;
            const __half* src = g_Wth + (size_t)(n0 + r) * 4096u + k0 + (q << 3);
            CP_ASYNC16(smem_u32(sb + r * 144 + q * 16), src);
        }
    };

#pragma unroll
    for (int p = 0; p < NSTAGE - 1; ++p) {
        issue_stage(p);
        CP_ASYNC_COMMIT();
    }

    const uint32_t smem_base = smem_u32(smem);

    for (int kc = 0; kc < 64; ++kc) {
        CP_ASYNC_WAIT2();
        __syncthreads();

        if (kc + NSTAGE - 1 < 64) {
            issue_stage(kc + NSTAGE - 1);
            CP_ASYNC_COMMIT();
        }

        const int s = kc % NSTAGE;
        const uint32_t saddr = smem_base + s * STAGE_BYTES;
        const uint32_t baddr = saddr + A_BYTES;

        uint32_t af[2][4], bf[8][2];
        ldmatrix_x4(af[0][0], af[0][1], af[0][2], af[0][3],
                    saddr + (unsigned)a_off0 * 2u);
        ldmatrix_x4(af[1][0], af[1][1], af[1][2], af[1][3],
                    saddr + (unsigned)a_off1 * 2u);
#pragma unroll
        for (int np = 0; np < 4; np++)
            ldmatrix_x4(bf[2 * np][0], bf[2 * np + 1][0],
                        bf[2 * np][1], bf[2 * np + 1][1],
                        baddr + (unsigned)b_off[np] * 2u);
#pragma unroll
        for (int mt = 0; mt < 2; mt++)
#pragma unroll
            for (int nt = 0; nt < 8; nt++)
                mma_f16_16n8k16(acc[mt][nt], af[mt], bf[nt]);
    }
    CP_ASYNC_WAIT0();
    __syncthreads();

    // K-split reduction: kh=1..3 dump partial layers, kh=0 folds.
    float* red = (float*)smem;    // 3 layers x 4 ws x 2048 floats = 96KB
    if (kh != 0) {
#pragma unroll
        for (int mt = 0; mt < 2; mt++)
#pragma unroll
            for (int nt = 0; nt < 8; nt++)
#pragma unroll
                for (int c = 0; c < 4; c++) {
                    const int r = mt * 32 + nt * 4 + c;
                    red[((kh - 1) * 4 + ws) * 2048 + r * 32 + lid] =
                        acc[mt][nt][c];
                }
    }
    __syncthreads();
    if (kh == 0) {
#pragma unroll
        for (int mt = 0; mt < 2; mt++)
#pragma unroll
            for (int nt = 0; nt < 8; nt++)
#pragma unroll
                for (int c = 0; c < 4; c++) {
                    const int r = mt * 32 + nt * 4 + c;
                    const int idx = ws * 2048 + r * 32 + lid;
                    acc[mt][nt][c] += red[idx]
                                    + red[4 * 2048 + idx]
                                    + red[8 * 2048 + idx];
                }

#pragma unroll
        for (int mt = 0; mt < 2; mt++) {
#pragma unroll
            for (int nt = 0; nt < 8; nt++) {
                const int g = n0 + wn + nt * 8 + (lid & 3) * 2;
                const float2 bv = *(const float2*)(bias + g);
                const int m_lo = m0 + wm + mt * 16 + (lid >> 2);
                const int m_hi = m_lo + 8;
                float2 v0 = { acc[mt][nt][0] + bv.x, acc[mt][nt][1] + bv.y };
                float2 v1 = { acc[mt][nt][2] + bv.x, acc[mt][nt][3] + bv.y };
                *(float2*)(out + ((size_t)(m_lo >> 5) << 22)
                               + (size_t)(2016 + (m_lo & 31)) * 1024 + g) = v0;
                *(float2*)(out + ((size_t)(m_hi >> 5) << 22)
                               + (size_t)(2016 + (m_hi & 31)) * 1024 + g) = v1;
            }
        }
    }
}

// ---------------------------------------------------------------------------
// Copy kernel: pure shifted memcpy, float4-vectorized, grid-stride.
// ---------------------------------------------------------------------------
__global__ void copy_kernel(const float4* __restrict__ inputs,
                            const float4* __restrict__ memory,
                            float4* __restrict__ out)
{
    const unsigned total = 32u * 4096u * 256u;
    const unsigned stride = gridDim.x * blockDim.x;
    for (unsigned v = blockIdx.x * blockDim.x + threadIdx.x; v < total; v += stride) {
        unsigned f4 = v & 255u;
        unsigned rg = v >> 8;
        unsigned b  = rg >> 12;
        unsigned r  = rg & 4095u;
        float4 val;
        if (r < 2016u) {
            val = memory[(b << 20) + ((r + 32u) << 8) + f4];
        } else if (r < 2048u) {
            continue;  // compression band written by GEMM kernel
        } else if (r < 3968u) {
            val = memory[(b << 20) + ((r + 128u) << 8) + f4];
        } else {
            val = inputs[(b << 15) + ((r - 3968u) << 8) + f4];
        }
        out[v] = val;
    }
}

// ---------------------------------------------------------------------------
// Launch: convert -> GEMM -> copy (serial).
// ---------------------------------------------------------------------------
extern "C" void kernel_launch(void* const* d_in, const int* in_sizes, int n_in,
                              void* d_out, int out_size)
{
    const float* inputs = (const float*)d_in[0];   // (32, 128, 1024)
    const float* memory = (const float*)d_in[1];   // (32, 4096, 1024)
    const float* conv_w = (const float*)d_in[2];   // (4, 1024, 1024)
    const float* conv_b = (const float*)d_in[3];   // (1024,)
    float* out = (float*)d_out;                    // (32, 4096, 1024)

    cudaFuncSetAttribute(gemm_f16,
                         cudaFuncAttributeMaxDynamicSharedMemorySize,
                         STAGE_BYTES * NSTAGE);

    convert_all<<<2048, 256>>>(memory, conv_w);
    gemm_f16<<<dim3(8, 16), NTHREADS, STAGE_BYTES * NSTAGE>>>(conv_b, out);
    copy_kernel<<<8192, 256>>>((const float4*)inputs, (const float4*)memory,
                               (float4*)out);
}